// round 12
// baseline (speedup 1.0000x reference)
#include <cuda_runtime.h>
#include <cuda_bf16.h>
#include <math_constants.h>

#define ROW_D      32000
#define ROW_D4     (ROW_D / 4)          // 8000 quads
#define CAP        3072
#define MAX_ROWS   2048
#define NTHREADS   512
#define NWARPS     (NTHREADS / 32)
#define KSLOTS     (CAP / NTHREADS)     // 6
#define SAMPLE_Q   4096                 // 16384 elements (64 KB) sampled
#define NITER      50
#define NEWTON_IT  8
#define FULLMASK   0xFFFFFFFFu
#define G_FULL     3072                 // 6*512 quads per group
#define TAIL0      6144
#define TAIL1      7680

// global scratch (static __device__ arrays are the sanctioned no-alloc path)
__device__ float  g_val[(size_t)MAX_ROWS * CAP];
__device__ int    g_idx[(size_t)MAX_ROWS * CAP];
__device__ int    g_cnt[MAX_ROWS];
__device__ float2 g_tau[MAX_ROWS];      // (tau_final, invS)

__device__ __forceinline__ float pfun(float z, float cexp, bool sq) {
    if (z <= 0.0f) return 0.0f;
    return sq ? z * z : powf(z, cexp);
}
__device__ __forceinline__ float max4(float4 v) {
    return fmaxf(fmaxf(v.x, v.y), fmaxf(v.z, v.w));
}

// ================= K1: pure-read scan + collect + Newton =================
__global__ __launch_bounds__(NTHREADS, 3)
void entmax_scan_kernel(const float* __restrict__ x,
                        const float* __restrict__ alpha_p)
{
    __shared__ float  s_val[CAP];
    __shared__ int    s_idx[CAP];
    __shared__ float2 s_red2[NWARPS];
    __shared__ float  s_redb[2][NWARPS];
    __shared__ int    s_cnt;
    __shared__ float  s_bcast;
    __shared__ float  s_tau;
    __shared__ float2 s_fin;

    const int tid  = threadIdx.x;
    const int lane = tid & 31;
    const int warp = tid >> 5;
    const int row  = blockIdx.x;

    const float alpha = *alpha_p;
    const float am1   = alpha - 1.0f;
    const float cexp  = 1.0f / am1;
    const bool  sq    = (cexp == 2.0f);

    const size_t row_off = (size_t)row * ROW_D;
    const float4* __restrict__ row4 = reinterpret_cast<const float4*>(x + row_off);

    if (tid == 0) s_cnt = 0;

    // ---- sampled max over first SAMPLE_Q quads ----
    float ms = -CUDART_INF_F;
    #pragma unroll
    for (int k = 0; k < SAMPLE_Q / NTHREADS; ++k)
        ms = fmaxf(ms, max4(row4[tid + k * NTHREADS]));
    #pragma unroll
    for (int o = 16; o; o >>= 1) ms = fmaxf(ms, __shfl_xor_sync(FULLMASK, ms, o));
    if (lane == 0) s_redb[0][warp] = ms;
    __syncthreads();
    if (warp == 0) {
        float mm = (lane < NWARPS) ? s_redb[0][lane] : -CUDART_INF_F;
        #pragma unroll
        for (int o = 16; o; o >>= 1) mm = fmaxf(mm, __shfl_xor_sync(FULLMASK, mm, o));
        if (lane == 0) s_bcast = mm;
    }
    __syncthreads();
    // conservative threshold: superset of {X > Xmax-1}; extras contribute exactly 0
    const float thr = s_bcast - cexp;

    // ---- ONE full-row read (6-deep batches): true max + collect ----
    float m = -CUDART_INF_F;
    #pragma unroll
    for (int g = 0; g < 2; ++g) {
        const int base = g * G_FULL + tid;
        float4 v[6];
        #pragma unroll
        for (int k = 0; k < 6; ++k) v[k] = row4[base + k * NTHREADS];
        float m01 = fmaxf(max4(v[0]), max4(v[1]));
        float m23 = fmaxf(max4(v[2]), max4(v[3]));
        float m45 = fmaxf(max4(v[4]), max4(v[5]));
        float mg  = fmaxf(m01, fmaxf(m23, m45));
        m = fmaxf(m, mg);
        if (mg > thr) {
            #pragma unroll
            for (int k = 0; k < 6; ++k) {
                if (max4(v[k]) > thr) {
                    const int idx = (base + k * NTHREADS) * 4;
                    const float4 q = v[k];
                    if (q.x > thr) { int p = atomicAdd(&s_cnt, 1); if (p < CAP) { s_val[p] = q.x * am1; s_idx[p] = idx + 0; } }
                    if (q.y > thr) { int p = atomicAdd(&s_cnt, 1); if (p < CAP) { s_val[p] = q.y * am1; s_idx[p] = idx + 1; } }
                    if (q.z > thr) { int p = atomicAdd(&s_cnt, 1); if (p < CAP) { s_val[p] = q.z * am1; s_idx[p] = idx + 2; } }
                    if (q.w > thr) { int p = atomicAdd(&s_cnt, 1); if (p < CAP) { s_val[p] = q.w * am1; s_idx[p] = idx + 3; } }
                }
            }
        }
    }
    {
        const int base = TAIL0 + tid;
        const bool bt = tid < (ROW_D4 - TAIL1);
        float4 v[4];
        #pragma unroll
        for (int k = 0; k < 3; ++k) v[k] = row4[base + k * NTHREADS];
        if (bt) v[3] = row4[TAIL1 + tid];
        float mg = fmaxf(max4(v[0]), fmaxf(max4(v[1]), max4(v[2])));
        if (bt) mg = fmaxf(mg, max4(v[3]));
        m = fmaxf(m, mg);
        if (mg > thr) {
            #pragma unroll
            for (int k = 0; k < 4; ++k) {
                const bool ok = (k < 3) || bt;
                if (ok && max4(v[k]) > thr) {
                    const int idx = ((k < 3) ? (base + k * NTHREADS) : (TAIL1 + tid)) * 4;
                    const float4 q = v[k];
                    if (q.x > thr) { int p = atomicAdd(&s_cnt, 1); if (p < CAP) { s_val[p] = q.x * am1; s_idx[p] = idx + 0; } }
                    if (q.y > thr) { int p = atomicAdd(&s_cnt, 1); if (p < CAP) { s_val[p] = q.y * am1; s_idx[p] = idx + 1; } }
                    if (q.z > thr) { int p = atomicAdd(&s_cnt, 1); if (p < CAP) { s_val[p] = q.z * am1; s_idx[p] = idx + 2; } }
                    if (q.w > thr) { int p = atomicAdd(&s_cnt, 1); if (p < CAP) { s_val[p] = q.w * am1; s_idx[p] = idx + 3; } }
                }
            }
        }
    }

    // ---- true-max reduce ----
    #pragma unroll
    for (int o = 16; o; o >>= 1) m = fmaxf(m, __shfl_xor_sync(FULLMASK, m, o));
    if (lane == 0) s_redb[1][warp] = m;
    __syncthreads();
    if (warp == 0) {
        float mm = (lane < NWARPS) ? s_redb[1][lane] : -CUDART_INF_F;
        #pragma unroll
        for (int o = 16; o; o >>= 1) mm = fmaxf(mm, __shfl_xor_sync(FULLMASK, mm, o));
        if (lane == 0) s_bcast = mm * am1;
    }
    __syncthreads();

    const float Xmax   = s_bcast;
    const float tau_lo = Xmax - 1.0f;
    const float tau_hi = Xmax - powf(1.0f / (float)ROW_D, am1);
    const int   cnt    = s_cnt;

    if (cnt <= CAP) {
        const int kmax = (cnt + NTHREADS - 1) / NTHREADS;
        for (int j = cnt + tid; j < kmax * NTHREADS; j += NTHREADS)
            s_val[j] = -CUDART_INF_F;
        if (tid == 0) s_tau = tau_lo + 0.5f * (tau_hi - tau_lo);
        __syncthreads();

        if (sq) {
            // safeguarded Newton on f(t)=sum (X-t)_+^2 - 1
            float lo = tau_lo, hi = tau_hi;
            for (int it = 0; it < NEWTON_IT; ++it) {
                const float tau = s_tau;
                float f_loc = 0.0f, g_loc = 0.0f;
                #pragma unroll
                for (int k = 0; k < KSLOTS; ++k) {
                    if (k < kmax) {
                        float zp = fmaxf(s_val[tid + k * NTHREADS] - tau, 0.0f);
                        f_loc = fmaf(zp, zp, f_loc);
                        g_loc += zp;
                    }
                }
                #pragma unroll
                for (int o = 16; o; o >>= 1) {
                    f_loc += __shfl_xor_sync(FULLMASK, f_loc, o);
                    g_loc += __shfl_xor_sync(FULLMASK, g_loc, o);
                }
                if (lane == 0) s_red2[warp] = make_float2(f_loc, g_loc);
                __syncthreads();
                if (warp == 0) {
                    float2 p2 = (lane < NWARPS) ? s_red2[lane] : make_float2(0.f, 0.f);
                    float F = p2.x, G = p2.y;
                    #pragma unroll
                    for (int o = 8; o; o >>= 1) {
                        F += __shfl_xor_sync(FULLMASK, F, o);
                        G += __shfl_xor_sync(FULLMASK, G, o);
                    }
                    if (lane == 0) {
                        float f = F - 1.0f;
                        if (f >= 0.0f) lo = tau; else hi = tau;
                        float tn = tau + f / (2.0f * G);
                        if (!(tn >= lo && tn <= hi)) tn = 0.5f * (lo + hi);
                        s_tau = tn;
                        if (it == NEWTON_IT - 1) s_fin = make_float2(tau, F);
                    }
                }
                __syncthreads();
            }
        } else {
            // general alpha: exact 50-iter bisection
            float f_lo_s = 0.0f, dm = 0.0f, tlo = tau_lo;
            {
                float acc = 0.0f;
                #pragma unroll
                for (int k = 0; k < KSLOTS; ++k)
                    if (k < kmax) acc += pfun(s_val[tid + k * NTHREADS] - tau_lo, cexp, sq);
                #pragma unroll
                for (int o = 16; o; o >>= 1) acc += __shfl_xor_sync(FULLMASK, acc, o);
                if (lane == 0) s_red2[warp] = make_float2(acc, 0.f);
                __syncthreads();
                if (warp == 0) {
                    float F = (lane < NWARPS) ? s_red2[lane].x : 0.0f;
                    #pragma unroll
                    for (int o = 8; o; o >>= 1) F += __shfl_xor_sync(FULLMASK, F, o);
                    if (lane == 0) { f_lo_s = F - 1.0f; dm = tau_hi - tau_lo; s_tau = tau_lo + 0.5f * dm; }
                }
                __syncthreads();
            }
            for (int it = 0; it < NITER; ++it) {
                const float tau = s_tau;
                float acc = 0.0f;
                #pragma unroll
                for (int k = 0; k < KSLOTS; ++k)
                    if (k < kmax) acc += pfun(s_val[tid + k * NTHREADS] - tau, cexp, sq);
                #pragma unroll
                for (int o = 16; o; o >>= 1) acc += __shfl_xor_sync(FULLMASK, acc, o);
                if (lane == 0) s_red2[warp] = make_float2(acc, 0.f);
                __syncthreads();
                if (warp == 0) {
                    float F = (lane < NWARPS) ? s_red2[lane].x : 0.0f;
                    #pragma unroll
                    for (int o = 8; o; o >>= 1) F += __shfl_xor_sync(FULLMASK, F, o);
                    if (lane == 0) {
                        if ((F - 1.0f) * f_lo_s >= 0.0f) tlo = tau;
                        dm *= 0.5f;
                        if (it == NITER - 1) s_fin = make_float2(tau, F);
                        else s_tau = tlo + 0.5f * dm;
                    }
                }
                __syncthreads();
            }
        }

        // publish results + candidate list
        if (tid == 0) {
            g_cnt[row] = cnt;
            g_tau[row] = make_float2(s_fin.x, 1.0f / s_fin.y);
        }
        const size_t gbase = (size_t)row * CAP;
        for (int j = tid; j < cnt; j += NTHREADS) {
            g_val[gbase + j] = s_val[j];
            g_idx[gbase + j] = s_idx[j];
        }
    } else {
        // fallback: exact full-row bisection; flag cnt=-1 for K2 full recompute
        float acc = 0.0f;
        for (int j = tid; j < ROW_D; j += NTHREADS)
            acc += pfun(x[row_off + j] * am1 - tau_lo, cexp, sq);
        #pragma unroll
        for (int o = 16; o; o >>= 1) acc += __shfl_xor_sync(FULLMASK, acc, o);
        if (lane == 0) s_redb[1][warp] = acc;
        __syncthreads();
        float f_lo = -1.0f;
        #pragma unroll
        for (int w = 0; w < NWARPS; ++w) f_lo += s_redb[1][w];

        float dm = tau_hi - tau_lo;
        float tlo = tau_lo, tau_m = tau_lo, fsum = 1.0f;
        for (int it = 0; it < NITER; ++it) {
            dm *= 0.5f;
            tau_m = tlo + dm;
            acc = 0.0f;
            for (int j = tid; j < ROW_D; j += NTHREADS)
                acc += pfun(x[row_off + j] * am1 - tau_m, cexp, sq);
            #pragma unroll
            for (int o = 16; o; o >>= 1) acc += __shfl_xor_sync(FULLMASK, acc, o);
            const int buf = it & 1;
            if (lane == 0) s_redb[buf][warp] = acc;
            __syncthreads();
            fsum = 0.0f;
            #pragma unroll
            for (int w = 0; w < NWARPS; ++w) fsum += s_redb[buf][w];
            if ((fsum - 1.0f) * f_lo >= 0.0f) tlo = tau_m;
        }
        if (tid == 0) {
            g_cnt[row] = -1;
            g_tau[row] = make_float2(tau_m, 1.0f / fsum);
        }
    }
}

// ================= K2: pure-store zero-fill + sparse scatter =================
__global__ __launch_bounds__(NTHREADS, 4)
void entmax_write_kernel(const float* __restrict__ x,
                         const float* __restrict__ alpha_p,
                         float* __restrict__ out)
{
    const int tid = threadIdx.x;
    const int row = blockIdx.x;

    const size_t row_off = (size_t)row * ROW_D;
    float*  __restrict__ orow  = out + row_off;
    float4* __restrict__ orow4 = reinterpret_cast<float4*>(orow);

    const int    cnt = g_cnt[row];
    const float2 tf  = g_tau[row];
    const float  tau = tf.x, invS = tf.y;

    if (cnt >= 0) {
        // zero-fill: pure store stream (15 full slots + tail)
        const float4 ZQ = make_float4(0.f, 0.f, 0.f, 0.f);
        #pragma unroll
        for (int k = 0; k < 15; ++k)
            __stcs(&orow4[tid + k * NTHREADS], ZQ);
        if (tid < (ROW_D4 - 15 * NTHREADS))
            __stcs(&orow4[15 * NTHREADS + tid], ZQ);
        __syncthreads();   // order zeros before scatter (block-wide)

        const float alpha = *alpha_p;
        const float am1   = alpha - 1.0f;
        const float cexp  = 1.0f / am1;
        const bool  sq    = (cexp == 2.0f);

        const size_t gbase = (size_t)row * CAP;
        for (int j = tid; j < cnt; j += NTHREADS) {
            float X = g_val[gbase + j];
            int   i = g_idx[gbase + j];
            orow[i] = pfun(X - tau, cexp, sq) * invS;
        }
    } else {
        // fallback full recompute (cnt overflow; ~never)
        const float alpha = *alpha_p;
        const float am1   = alpha - 1.0f;
        const float cexp  = 1.0f / am1;
        const bool  sq    = (cexp == 2.0f);
        const float4* __restrict__ row4 = reinterpret_cast<const float4*>(x + row_off);
        for (int i = tid; i < ROW_D4; i += NTHREADS) {
            float4 v = row4[i];
            float4 r;
            r.x = pfun(v.x * am1 - tau, cexp, sq) * invS;
            r.y = pfun(v.y * am1 - tau, cexp, sq) * invS;
            r.z = pfun(v.z * am1 - tau, cexp, sq) * invS;
            r.w = pfun(v.w * am1 - tau, cexp, sq) * invS;
            __stcs(&orow4[i], r);
        }
    }
}

extern "C" void kernel_launch(void* const* d_in, const int* in_sizes, int n_in,
                              void* d_out, int out_size)
{
    const float* x     = (const float*)d_in[0];
    const float* alpha = (const float*)d_in[1];
    float*       out   = (float*)d_out;

    const int rows = in_sizes[0] / ROW_D;
    entmax_scan_kernel<<<rows, NTHREADS>>>(x, alpha);
    entmax_write_kernel<<<rows, NTHREADS>>>(x, alpha, out);
}

// round 13
// speedup vs baseline: 2.2303x; 2.2303x over previous
#include <cuda_runtime.h>
#include <cuda_bf16.h>
#include <math_constants.h>

#define ROW_D      32000
#define ROW_D4     (ROW_D / 4)          // 8000 quads
#define CAP        3072
#define NTHREADS   512
#define NWARPS     (NTHREADS / 32)
#define NST        480                  // storer threads (warps 1-15)
#define NITER      50
#define NEWTON_IT  8
#define FULLMASK   0xFFFFFFFFu
#define G_FULL     3072                 // 6*512 quads per group
#define TAIL0      6144
#define TAIL1      7680

__device__ __forceinline__ float pfun(float z, float cexp, bool sq) {
    if (z <= 0.0f) return 0.0f;
    return sq ? z * z : powf(z, cexp);
}
__device__ __forceinline__ float max4(float4 v) {
    return fmaxf(fmaxf(v.x, v.y), fmaxf(v.z, v.w));
}

__global__ __launch_bounds__(NTHREADS, 3)
void entmax_bisect_kernel(const float* __restrict__ x,
                          const float* __restrict__ alpha_p,
                          float* __restrict__ out)
{
    __shared__ float  s_val[CAP];
    __shared__ int    s_idx[CAP];
    __shared__ float  s_redb[2][NWARPS];
    __shared__ int    s_cnt;
    __shared__ float  s_max;
    __shared__ float2 s_fin;   // (tau_final, fsum)

    const int tid  = threadIdx.x;
    const int lane = tid & 31;
    const int warp = tid >> 5;

    const float alpha = *alpha_p;
    const float am1   = alpha - 1.0f;
    const float cexp  = 1.0f / am1;
    const bool  sq    = (cexp == 2.0f);

    const size_t row_off = (size_t)blockIdx.x * ROW_D;
    const float4* __restrict__ row4 = reinterpret_cast<const float4*>(x + row_off);
    float*        __restrict__ orow  = out + row_off;
    float4*       __restrict__ orow4 = reinterpret_cast<float4*>(orow);

    if (tid == 0) s_cnt = 0;

    // ---- Phase 1: row max, read-only, 6 loads in flight per thread (R9) ----
    float m = -CUDART_INF_F;
    #pragma unroll
    for (int g = 0; g < 2; ++g) {
        const int base = g * G_FULL + tid;
        float4 v0 = row4[base];
        float4 v1 = row4[base +     NTHREADS];
        float4 v2 = row4[base + 2 * NTHREADS];
        float4 v3 = row4[base + 3 * NTHREADS];
        float4 v4 = row4[base + 4 * NTHREADS];
        float4 v5 = row4[base + 5 * NTHREADS];
        float a = fmaxf(max4(v0), max4(v1));
        float b = fmaxf(max4(v2), max4(v3));
        float c = fmaxf(max4(v4), max4(v5));
        m = fmaxf(m, fmaxf(a, fmaxf(b, c)));
    }
    {
        const int base = TAIL0 + tid;
        float4 v0 = row4[base];
        float4 v1 = row4[base +     NTHREADS];
        float4 v2 = row4[base + 2 * NTHREADS];
        float t = fmaxf(max4(v0), fmaxf(max4(v1), max4(v2)));
        if (tid < (ROW_D4 - TAIL1)) t = fmaxf(t, max4(row4[TAIL1 + tid]));
        m = fmaxf(m, t);
    }
    #pragma unroll
    for (int o = 16; o; o >>= 1) m = fmaxf(m, __shfl_xor_sync(FULLMASK, m, o));
    if (lane == 0) s_redb[0][warp] = m;
    __syncthreads();
    if (warp == 0) {
        float mm = (lane < NWARPS) ? s_redb[0][lane] : -CUDART_INF_F;
        #pragma unroll
        for (int o = 16; o; o >>= 1) mm = fmaxf(mm, __shfl_xor_sync(FULLMASK, mm, o));
        if (lane == 0) s_max = mm * am1;
    }
    __syncthreads();

    const float Xmax   = s_max;
    const float tau_lo = Xmax - 1.0f;                 // candidates: X > tau_lo
    const float thr_x  = tau_lo / am1;                // same test in raw-x space (am1 > 0)
    const float tau_hi = Xmax - powf(1.0f / (float)ROW_D, am1);

    // ---- Phase 2: L2 re-read (evict-first) + collect — NO stores here ----
    #pragma unroll
    for (int g = 0; g < 2; ++g) {
        const int base = g * G_FULL + tid;
        float4 v[6];
        #pragma unroll
        for (int k = 0; k < 6; ++k) v[k] = __ldcs(&row4[base + k * NTHREADS]);
        #pragma unroll
        for (int k = 0; k < 6; ++k) {
            if (max4(v[k]) > thr_x) {      // rare
                const int idx = (base + k * NTHREADS) * 4;
                const float4 q = v[k];
                if (q.x > thr_x) { int p = atomicAdd(&s_cnt, 1); if (p < CAP) { s_val[p] = q.x * am1; s_idx[p] = idx + 0; } }
                if (q.y > thr_x) { int p = atomicAdd(&s_cnt, 1); if (p < CAP) { s_val[p] = q.y * am1; s_idx[p] = idx + 1; } }
                if (q.z > thr_x) { int p = atomicAdd(&s_cnt, 1); if (p < CAP) { s_val[p] = q.z * am1; s_idx[p] = idx + 2; } }
                if (q.w > thr_x) { int p = atomicAdd(&s_cnt, 1); if (p < CAP) { s_val[p] = q.w * am1; s_idx[p] = idx + 3; } }
            }
        }
    }
    {
        const int base = TAIL0 + tid;
        const bool bt = tid < (ROW_D4 - TAIL1);
        float4 v[4];
        #pragma unroll
        for (int k = 0; k < 3; ++k) v[k] = __ldcs(&row4[base + k * NTHREADS]);
        if (bt) v[3] = __ldcs(&row4[TAIL1 + tid]);
        #pragma unroll
        for (int k = 0; k < 4; ++k) {
            const bool ok = (k < 3) || bt;
            if (ok && max4(v[k]) > thr_x) {
                const int idx = ((k < 3) ? (base + k * NTHREADS) : (TAIL1 + tid)) * 4;
                const float4 q = v[k];
                if (q.x > thr_x) { int p = atomicAdd(&s_cnt, 1); if (p < CAP) { s_val[p] = q.x * am1; s_idx[p] = idx + 0; } }
                if (q.y > thr_x) { int p = atomicAdd(&s_cnt, 1); if (p < CAP) { s_val[p] = q.y * am1; s_idx[p] = idx + 1; } }
                if (q.z > thr_x) { int p = atomicAdd(&s_cnt, 1); if (p < CAP) { s_val[p] = q.z * am1; s_idx[p] = idx + 2; } }
                if (q.w > thr_x) { int p = atomicAdd(&s_cnt, 1); if (p < CAP) { s_val[p] = q.w * am1; s_idx[p] = idx + 3; } }
            }
        }
    }
    __syncthreads();
    const int cnt = s_cnt;

    if (cnt <= CAP) {
        // ---- Phase 3 (warp-specialized, overlapped):
        //      warp 0: warp-synchronous solver (no block barriers)
        //      warps 1-15: zero-fill store sweep
        if (warp == 0) {
            if (sq) {
                // safeguarded Newton on f(t)=sum (X-t)_+^2 - 1 (convex, decreasing)
                float lo = tau_lo, hi = tau_hi;
                float tau = tau_lo + 0.5f * (tau_hi - tau_lo);
                float tauf = tau, Ff = 1.0f;
                for (int it = 0; it < NEWTON_IT; ++it) {
                    float f_loc = 0.0f, g_loc = 0.0f;
                    for (int j = lane; j < cnt; j += 32) {
                        float zp = fmaxf(s_val[j] - tau, 0.0f);
                        f_loc = fmaf(zp, zp, f_loc);
                        g_loc += zp;
                    }
                    #pragma unroll
                    for (int o = 16; o; o >>= 1) {
                        f_loc += __shfl_xor_sync(FULLMASK, f_loc, o);
                        g_loc += __shfl_xor_sync(FULLMASK, g_loc, o);
                    }
                    // all lanes hold identical F,G -> identical control flow
                    float f = f_loc - 1.0f;
                    if (f >= 0.0f) lo = tau; else hi = tau;
                    float tn = tau + f / (2.0f * g_loc);
                    if (!(tn >= lo && tn <= hi)) tn = 0.5f * (lo + hi);
                    tauf = tau; Ff = f_loc;
                    tau = tn;
                }
                if (lane == 0) s_fin = make_float2(tauf, Ff);
            } else {
                // general alpha: exact 50-iter bisection, warp-synchronous
                float acc = 0.0f;
                for (int j = lane; j < cnt; j += 32)
                    acc += pfun(s_val[j] - tau_lo, cexp, sq);
                #pragma unroll
                for (int o = 16; o; o >>= 1) acc += __shfl_xor_sync(FULLMASK, acc, o);
                const float f_lo = acc - 1.0f;

                float dm = tau_hi - tau_lo;
                float tlo = tau_lo, tau_m = tau_lo, fsum = 1.0f;
                for (int it = 0; it < NITER; ++it) {
                    dm *= 0.5f;
                    tau_m = tlo + dm;
                    acc = 0.0f;
                    for (int j = lane; j < cnt; j += 32)
                        acc += pfun(s_val[j] - tau_m, cexp, sq);
                    #pragma unroll
                    for (int o = 16; o; o >>= 1) acc += __shfl_xor_sync(FULLMASK, acc, o);
                    fsum = acc;
                    if ((fsum - 1.0f) * f_lo >= 0.0f) tlo = tau_m;
                }
                if (lane == 0) s_fin = make_float2(tau_m, fsum);
            }
        } else {
            // zero-fill: 480 threads, 16 full slots + tail
            const int stid = tid - 32;
            const float4 ZQ = make_float4(0.f, 0.f, 0.f, 0.f);
            #pragma unroll
            for (int k = 0; k < 16; ++k)
                __stcs(&orow4[stid + k * NST], ZQ);
            if (stid < (ROW_D4 - 16 * NST))
                __stcs(&orow4[16 * NST + stid], ZQ);
        }
        __syncthreads();   // zeros + solver result visible block-wide

        // ---- Phase 4: scatter nonzeros (all threads) ----
        const float tauf = s_fin.x;
        const float invS = 1.0f / s_fin.y;
        if (sq) {
            for (int j = tid; j < cnt; j += NTHREADS) {
                float zp = fmaxf(s_val[j] - tauf, 0.0f);
                __stcs(&orow[s_idx[j]], zp * zp * invS);
            }
        } else {
            for (int j = tid; j < cnt; j += NTHREADS)
                __stcs(&orow[s_idx[j]], pfun(s_val[j] - tauf, cexp, sq) * invS);
        }
    } else {
        // ---- Fallback: full-row block-wide bisection (cnt > CAP; ~never) ----
        float acc = 0.0f;
        for (int j = tid; j < ROW_D; j += NTHREADS)
            acc += pfun(x[row_off + j] * am1 - tau_lo, cexp, sq);
        #pragma unroll
        for (int o = 16; o; o >>= 1) acc += __shfl_xor_sync(FULLMASK, acc, o);
        if (lane == 0) s_redb[1][warp] = acc;
        __syncthreads();
        float f_lo = -1.0f;
        #pragma unroll
        for (int w = 0; w < NWARPS; ++w) f_lo += s_redb[1][w];

        float dm = tau_hi - tau_lo;
        float tlo = tau_lo, tau_m = tau_lo, fsum = 1.0f;

        for (int it = 0; it < NITER; ++it) {
            dm *= 0.5f;
            tau_m = tlo + dm;
            acc = 0.0f;
            for (int j = tid; j < ROW_D; j += NTHREADS)
                acc += pfun(x[row_off + j] * am1 - tau_m, cexp, sq);
            #pragma unroll
            for (int o = 16; o; o >>= 1) acc += __shfl_xor_sync(FULLMASK, acc, o);
            const int buf = it & 1;
            if (lane == 0) s_redb[buf][warp] = acc;
            __syncthreads();
            fsum = 0.0f;
            #pragma unroll
            for (int w = 0; w < NWARPS; ++w) fsum += s_redb[buf][w];
            if ((fsum - 1.0f) * f_lo >= 0.0f) tlo = tau_m;
        }

        const float invS = 1.0f / fsum;
        for (int i = tid; i < ROW_D4; i += NTHREADS) {
            float4 v = row4[i];
            float4 r;
            r.x = pfun(v.x * am1 - tau_m, cexp, sq) * invS;
            r.y = pfun(v.y * am1 - tau_m, cexp, sq) * invS;
            r.z = pfun(v.z * am1 - tau_m, cexp, sq) * invS;
            r.w = pfun(v.w * am1 - tau_m, cexp, sq) * invS;
            __stcs(&orow4[i], r);
        }
    }
}

extern "C" void kernel_launch(void* const* d_in, const int* in_sizes, int n_in,
                              void* d_out, int out_size)
{
    const float* x     = (const float*)d_in[0];
    const float* alpha = (const float*)d_in[1];
    float*       out   = (float*)d_out;

    const int rows = in_sizes[0] / ROW_D;
    entmax_bisect_kernel<<<rows, NTHREADS>>>(x, alpha, out);
}